// round 1
// baseline (speedup 1.0000x reference)
#include <cuda_runtime.h>
#include <math.h>
#include <stdint.h>

// ---------------- static config ----------------
#define BATCH  2
#define DD     8
#define HH     128
#define WW_    128
#define CDIM   96
#define HEADS  3
#define HDIM   32
#define INNER  96          // HEADS*HDIM
#define NWIN   1024        // (8/2)*(128/8)*(128/8)
#define NTOK   128         // 2*8*8
#define MROWS  (BATCH*NWIN*NTOK)   // 262144
#define MLPD   384
#define QKVN   288
#define ATT_SCALE 0.17677669529663687f  // 32^-0.5

// ---------------- scratch (static device globals; allocation-free) ----------------
__device__ float g_hw  [(size_t)MROWS * CDIM];
__device__ float g_qkv [(size_t)MROWS * QKVN];
__device__ float g_attn[(size_t)MROWS * INNER];
__device__ float g_h2  [(size_t)MROWS * CDIM];
__device__ float g_mlp [(size_t)MROWS * MLPD];

// window-order row -> natural token index (this is BOTH the gather source for
// roll(-shift)+partition AND the scatter target for reverse+roll(+shift))
__device__ __forceinline__ size_t nat_index(int r) {
    int bb  = r >> 17;           // / (NWIN*NTOK)
    int rem = r & 131071;
    int wdx = rem >> 7, n = rem & 127;
    int wz = wdx >> 8, wy = (wdx >> 4) & 15, wx = wdx & 15;
    int td = n >> 6,  th = (n >> 3) & 7,   tw = n & 7;
    int sd = (wz * 2 + td + 1) & 7;        // (+shift) mod D
    int sh = (wy * 8 + th + 4) & 127;
    int sw = (wx * 8 + tw + 4) & 127;
    return ((((size_t)bb * 8 + sd) << 7) | sh) << 7 | sw;
}

__device__ __forceinline__ float gelu_tanh(float v) {
    float c = v + 0.044715f * v * v * v;
    return 0.5f * v * (1.0f + tanhf(0.7978845608028654f * c));
}

// ---------------- LayerNorm (warp per token). GATHER=true also does roll+partition.
template<bool GATHER>
__global__ void ln_kernel(const float* __restrict__ x,
                          const float* __restrict__ gamma,
                          const float* __restrict__ beta,
                          float* __restrict__ out) {
    int warp = (blockIdx.x * blockDim.x + threadIdx.x) >> 5;
    int lane = threadIdx.x & 31;
    if (warp >= MROWS) return;
    size_t src = GATHER ? nat_index(warp) : (size_t)warp;
    const float* xp = x + src * CDIM;
    float v0 = xp[lane], v1 = xp[lane + 32], v2 = xp[lane + 64];
    float s = v0 + v1 + v2;
#pragma unroll
    for (int o = 16; o; o >>= 1) s += __shfl_xor_sync(0xffffffffu, s, o);
    float mu = s * (1.0f / 96.0f);
    float d0 = v0 - mu, d1 = v1 - mu, d2 = v2 - mu;
    float q = d0 * d0 + d1 * d1 + d2 * d2;
#pragma unroll
    for (int o = 16; o; o >>= 1) q += __shfl_xor_sync(0xffffffffu, q, o);
    float rs = rsqrtf(q * (1.0f / 96.0f) + 1e-5f);
    float* op = out + (size_t)warp * CDIM;
    op[lane]      = d0 * rs * gamma[lane]      + beta[lane];
    op[lane + 32] = d1 * rs * gamma[lane + 32] + beta[lane + 32];
    op[lane + 64] = d2 * rs * gamma[lane + 64] + beta[lane + 64];
}

// ---------------- generic 64x64 tiled fp32 GEMM, C = A[M,K] @ B[K,N] + epilogue
// MODE 0: store plain            (qkv)
// MODE 1: +bias, gelu, store     (fc1)
// MODE 2: +bias, +res[nat], scatter to nat index   (attn out-proj + reverse + residual)
// MODE 3: +bias, C += v (read-modify-write)        (fc2 + residual, C pre-holds x_new)
template<int MODE>
__global__ void gemm_kernel(const float* __restrict__ A, const float* __restrict__ B,
                            float* __restrict__ C, int N, int K,
                            const float* __restrict__ bias,
                            const float* __restrict__ res) {
    __shared__ float As[64][17];
    __shared__ float Bs[16][65];
    int tid = threadIdx.x;
    int tx = tid & 15, ty = tid >> 4;       // 16x16 threads
    int row0 = blockIdx.y * 64, col0 = blockIdx.x * 64;
    float acc[4][4] = {};
    for (int k0 = 0; k0 < K; k0 += 16) {
#pragma unroll
        for (int i = 0; i < 4; i++) {
            int idx = tid + i * 256;
            int r = idx >> 4, c = idx & 15;
            As[r][c] = A[(size_t)(row0 + r) * K + k0 + c];
        }
#pragma unroll
        for (int i = 0; i < 4; i++) {
            int idx = tid + i * 256;
            int r = idx >> 6, c = idx & 63;
            int gc = col0 + c;
            Bs[r][c] = (gc < N) ? B[(size_t)(k0 + r) * N + gc] : 0.0f;
        }
        __syncthreads();
#pragma unroll
        for (int kk = 0; kk < 16; kk++) {
            float a[4], bf[4];
#pragma unroll
            for (int i = 0; i < 4; i++) a[i]  = As[ty * 4 + i][kk];
#pragma unroll
            for (int j = 0; j < 4; j++) bf[j] = Bs[kk][tx * 4 + j];
#pragma unroll
            for (int i = 0; i < 4; i++)
#pragma unroll
                for (int j = 0; j < 4; j++) acc[i][j] += a[i] * bf[j];
        }
        __syncthreads();
    }
#pragma unroll
    for (int i = 0; i < 4; i++) {
        int row = row0 + ty * 4 + i;
        size_t nat = 0;
        if (MODE == 2) nat = nat_index(row) * (size_t)CDIM;
#pragma unroll
        for (int j = 0; j < 4; j++) {
            int col = col0 + tx * 4 + j;
            if (col >= N) continue;
            float v = acc[i][j];
            if (MODE == 0) {
                C[(size_t)row * N + col] = v;
            } else if (MODE == 1) {
                C[(size_t)row * N + col] = gelu_tanh(v + bias[col]);
            } else if (MODE == 2) {
                size_t o = nat + col;
                C[o] = res[o] + v + bias[col];
            } else { // MODE 3
                size_t o = (size_t)row * N + col;
                C[o] = C[o] + v + bias[col];
            }
        }
    }
}

// ---------------- attention: one block per (batch, window, head), 128 threads
__device__ __forceinline__ int region3(int d, int h, int w) {
    int rd = (d < 6)   ? 0 : (d < 7   ? 1 : 2);
    int rh = (h < 120) ? 0 : (h < 124 ? 1 : 2);
    int rw = (w < 120) ? 0 : (w < 124 ? 1 : 2);
    return rd * 9 + rh * 3 + rw;
}

#define ATTN_SMEM ((128*33 + 128*33 + 128*129 + 675 + 128) * 4)

__global__ void attn_kernel(const float* __restrict__ qkv,
                            const float* __restrict__ rel_bias,
                            float* __restrict__ attn_out) {
    extern __shared__ float sm[];
    float* ks     = sm;                  // [128][33]
    float* vs     = ks + 128 * 33;       // [128][33]
    float* ps     = vs + 128 * 33;       // [128][129]
    float* bias_s = ps + 128 * 129;      // [675]
    int*   reg_s  = (int*)(bias_s + 675);

    int blk  = blockIdx.x;
    int head = blk % HEADS;
    int bw   = blk / HEADS;
    int w    = bw % NWIN;
    int b    = bw / NWIN;
    int i    = threadIdx.x;              // query row, 0..127

    const float* base = qkv + (size_t)(b * NWIN + w) * NTOK * QKVN;

    // stage K and V tiles (coalesced)
    for (int idx = i; idx < 128 * 32; idx += 128) {
        int r = idx >> 5, c = idx & 31;
        ks[r * 33 + c] = base[(size_t)r * QKVN + 96  + head * 32 + c];
        vs[r * 33 + c] = base[(size_t)r * QKVN + 192 + head * 32 + c];
    }
    // stage this head's rel-bias column
    for (int t = i; t < 675; t += 128) bias_s[t] = rel_bias[t * 3 + head];
    // region id of each token of this window (for the shift mask)
    {
        int wz = w >> 8, wy = (w >> 4) & 15, wx = w & 15;
        int td = i >> 6, th = (i >> 3) & 7, tw = i & 7;
        reg_s[i] = region3(wz * 2 + td, wy * 8 + th, wx * 8 + tw);
    }
    // my q row in registers
    float qr[32];
#pragma unroll
    for (int dd = 0; dd < 32; dd++) qr[dd] = base[(size_t)i * QKVN + head * 32 + dd];
    __syncthreads();

    int myreg = reg_s[i];
    int di = i >> 6, hi = (i >> 3) & 7, wi = i & 7;

    float* prow = ps + i * 129;
    float mx = -1e30f;
    for (int j = 0; j < 128; j++) {
        const float* kj = ks + j * 33;
        float dot = 0.0f;
#pragma unroll
        for (int dd = 0; dd < 32; dd++) dot += qr[dd] * kj[dd];
        int dj = j >> 6, hj = (j >> 3) & 7, wj = j & 7;
        int bidx = (di - dj + 1) * 225 + (hi - hj + 7) * 15 + (wi - wj + 7);
        float sv = dot * ATT_SCALE + bias_s[bidx];
        sv += (reg_s[j] == myreg) ? 0.0f : -1e9f;
        prow[j] = sv;
        mx = fmaxf(mx, sv);
    }
    float den = 0.0f;
    for (int j = 0; j < 128; j++) {
        float p = __expf(prow[j] - mx);
        prow[j] = p;
        den += p;
    }
    float inv = 1.0f / den;
    float o[32] = {};
    for (int j = 0; j < 128; j++) {
        float p = prow[j];
        const float* vj = vs + j * 33;
#pragma unroll
        for (int dd = 0; dd < 32; dd++) o[dd] += p * vj[dd];
    }
    float* op = attn_out + (size_t)((b * NWIN + w) * NTOK + i) * INNER + head * 32;
#pragma unroll
    for (int dd = 0; dd < 32; dd++) op[dd] = o[dd] * inv;
}

// ---------------- launch ----------------
extern "C" void kernel_launch(void* const* d_in, const int* in_sizes, int n_in,
                              void* d_out, int out_size) {
    const float* x      = (const float*)d_in[0];
    const float* gamma1 = (const float*)d_in[1];
    const float* beta1  = (const float*)d_in[2];
    const float* w_qkv  = (const float*)d_in[3];
    const float* w_out  = (const float*)d_in[4];
    const float* b_out  = (const float*)d_in[5];
    const float* relb   = (const float*)d_in[6];
    const float* gamma2 = (const float*)d_in[7];
    const float* beta2  = (const float*)d_in[8];
    const float* w1     = (const float*)d_in[9];
    const float* b1     = (const float*)d_in[10];
    const float* w2     = (const float*)d_in[11];
    const float* b2     = (const float*)d_in[12];
    float* out = (float*)d_out;

    float *hw, *qkv, *attn, *h2, *mlp;
    cudaGetSymbolAddress((void**)&hw,   g_hw);
    cudaGetSymbolAddress((void**)&qkv,  g_qkv);
    cudaGetSymbolAddress((void**)&attn, g_attn);
    cudaGetSymbolAddress((void**)&h2,   g_h2);
    cudaGetSymbolAddress((void**)&mlp,  g_mlp);

    cudaFuncSetAttribute(attn_kernel, cudaFuncAttributeMaxDynamicSharedMemorySize,
                         ATTN_SMEM);

    // 1) LN1 + roll + window partition (gather)
    ln_kernel<true><<<MROWS / 8, 256>>>(x, gamma1, beta1, hw);
    // 2) QKV GEMM  [M,96] @ [96,288]
    gemm_kernel<0><<<dim3((QKVN + 63) / 64, MROWS / 64), 256>>>(
        hw, w_qkv, qkv, QKVN, CDIM, nullptr, nullptr);
    // 3) windowed attention
    attn_kernel<<<BATCH * NWIN * HEADS, 128, ATTN_SMEM>>>(qkv, relb, attn);
    // 4) out-proj + window reverse + roll back + residual  -> d_out = x_new
    gemm_kernel<2><<<dim3(2, MROWS / 64), 256>>>(
        attn, w_out, out, CDIM, INNER, b_out, x);
    // 5) LN2 (natural order)
    ln_kernel<false><<<MROWS / 8, 256>>>(out, gamma2, beta2, h2);
    // 6) fc1 + bias + gelu
    gemm_kernel<1><<<dim3(MLPD / 64, MROWS / 64), 256>>>(
        h2, w1, mlp, MLPD, CDIM, b1, nullptr);
    // 7) fc2 + bias + residual (d_out += ...)
    gemm_kernel<3><<<dim3(2, MROWS / 64), 256>>>(
        mlp, w2, out, CDIM, MLPD, b2, nullptr);
}

// round 2
// speedup vs baseline: 1.2299x; 1.2299x over previous
#include <cuda_runtime.h>
#include <math.h>
#include <stdint.h>

// ---------------- static config ----------------
#define BATCH  2
#define CDIM   96
#define HEADS  3
#define INNER  96
#define NWIN   1024
#define NTOK   128
#define MROWS  (BATCH*NWIN*NTOK)   // 262144
#define MLPD   384
#define QKVN   288
#define ATT_SCALE 0.17677669529663687f

// ---------------- scratch ----------------
__device__ float g_hw  [(size_t)MROWS * CDIM];
__device__ float g_qkv [(size_t)MROWS * QKVN];
__device__ float g_attn[(size_t)MROWS * INNER];
__device__ float g_h2  [(size_t)MROWS * CDIM];
__device__ float g_mlp [(size_t)MROWS * MLPD];

__device__ __forceinline__ size_t nat_index(int r) {
    int bb  = r >> 17;
    int rem = r & 131071;
    int wdx = rem >> 7, n = rem & 127;
    int wz = wdx >> 8, wy = (wdx >> 4) & 15, wx = wdx & 15;
    int td = n >> 6,  th = (n >> 3) & 7,   tw = n & 7;
    int sd = (wz * 2 + td + 1) & 7;
    int sh = (wy * 8 + th + 4) & 127;
    int sw = (wx * 8 + tw + 4) & 127;
    return ((((size_t)bb * 8 + sd) << 7) | sh) << 7 | sw;
}

__device__ __forceinline__ float gelu_tanh(float v) {
    float c = v + 0.044715f * v * v * v;
    return 0.5f * v * (1.0f + tanhf(0.7978845608028654f * c));
}

__device__ __forceinline__ uint32_t f2tf32(float x) {
    uint32_t r;
    asm("cvt.rna.tf32.f32 %0, %1;" : "=r"(r) : "f"(x));
    return r;
}

// ---------------- LayerNorm (warp per token) ----------------
template<bool GATHER>
__global__ void ln_kernel(const float* __restrict__ x,
                          const float* __restrict__ gamma,
                          const float* __restrict__ beta,
                          float* __restrict__ out) {
    int warp = (blockIdx.x * blockDim.x + threadIdx.x) >> 5;
    int lane = threadIdx.x & 31;
    if (warp >= MROWS) return;
    size_t src = GATHER ? nat_index(warp) : (size_t)warp;
    const float* xp = x + src * CDIM;
    float v0 = xp[lane], v1 = xp[lane + 32], v2 = xp[lane + 64];
    float s = v0 + v1 + v2;
#pragma unroll
    for (int o = 16; o; o >>= 1) s += __shfl_xor_sync(0xffffffffu, s, o);
    float mu = s * (1.0f / 96.0f);
    float d0 = v0 - mu, d1 = v1 - mu, d2 = v2 - mu;
    float q = d0 * d0 + d1 * d1 + d2 * d2;
#pragma unroll
    for (int o = 16; o; o >>= 1) q += __shfl_xor_sync(0xffffffffu, q, o);
    float rs = rsqrtf(q * (1.0f / 96.0f) + 1e-5f);
    float* op = out + (size_t)warp * CDIM;
    op[lane]      = d0 * rs * gamma[lane]      + beta[lane];
    op[lane + 32] = d1 * rs * gamma[lane + 32] + beta[lane + 32];
    op[lane + 64] = d2 * rs * gamma[lane + 64] + beta[lane + 64];
}

// ---------------- tf32 tensor-core GEMM: 128x64 tile, BK=32, 8 warps ----------------
// MODE 0: plain store (qkv)   MODE 1: +bias+gelu (fc1)
// MODE 2: +bias + res[nat], scatter (out-proj)   MODE 3: +bias, C+= (fc2)
template<int MODE>
__global__ void __launch_bounds__(256)
gemm_tc(const float* __restrict__ A, const float* __restrict__ B,
        float* __restrict__ C, int N, int K,
        const float* __restrict__ bias, const float* __restrict__ res) {
    __shared__ uint32_t As[128][36];   // bank: 4g+t -> conflict-free
    __shared__ uint32_t Bs[32][72];    // bank: 8t+g -> conflict-free
    int tid  = threadIdx.x;
    int lane = tid & 31, wid = tid >> 5;
    int wm = wid & 3, wn = wid >> 2;           // 4x2 warps -> 32x32 each
    int g = lane >> 2, t = lane & 3;
    int row0 = blockIdx.y * 128, col0 = blockIdx.x * 64;

    float acc[2][4][4];
#pragma unroll
    for (int a = 0; a < 2; a++)
#pragma unroll
        for (int b = 0; b < 4; b++)
#pragma unroll
            for (int c = 0; c < 4; c++) acc[a][b][c] = 0.0f;

    for (int k0 = 0; k0 < K; k0 += 32) {
        // A tile 128x32 (rows always valid, K%32==0)
#pragma unroll
        for (int i = 0; i < 16; i++) {
            int lin = tid + i * 256;
            int r = lin >> 5, c = lin & 31;
            As[r][c] = f2tf32(A[(size_t)(row0 + r) * K + k0 + c]);
        }
        // B tile 32x64 (guard cols)
#pragma unroll
        for (int i = 0; i < 8; i++) {
            int lin = tid + i * 256;
            int r = lin >> 6, c = lin & 63;
            int gc = col0 + c;
            Bs[r][c] = (gc < N) ? f2tf32(B[(size_t)(k0 + r) * N + gc]) : 0u;
        }
        __syncthreads();
#pragma unroll
        for (int kk = 0; kk < 4; kk++) {
            uint32_t af[2][4], bf[4][2];
#pragma unroll
            for (int mi = 0; mi < 2; mi++) {
                int r = wm * 32 + mi * 16;
                af[mi][0] = As[r + g    ][kk * 8 + t];
                af[mi][1] = As[r + g + 8][kk * 8 + t];
                af[mi][2] = As[r + g    ][kk * 8 + t + 4];
                af[mi][3] = As[r + g + 8][kk * 8 + t + 4];
            }
#pragma unroll
            for (int ni = 0; ni < 4; ni++) {
                int cc = wn * 32 + ni * 8 + g;
                bf[ni][0] = Bs[kk * 8 + t    ][cc];
                bf[ni][1] = Bs[kk * 8 + t + 4][cc];
            }
#pragma unroll
            for (int mi = 0; mi < 2; mi++)
#pragma unroll
                for (int ni = 0; ni < 4; ni++) {
                    asm volatile(
                        "mma.sync.aligned.m16n8k8.row.col.f32.tf32.tf32.f32 "
                        "{%0,%1,%2,%3}, {%4,%5,%6,%7}, {%8,%9}, {%0,%1,%2,%3};\n"
                        : "+f"(acc[mi][ni][0]), "+f"(acc[mi][ni][1]),
                          "+f"(acc[mi][ni][2]), "+f"(acc[mi][ni][3])
                        : "r"(af[mi][0]), "r"(af[mi][1]), "r"(af[mi][2]), "r"(af[mi][3]),
                          "r"(bf[ni][0]), "r"(bf[ni][1]));
                }
        }
        __syncthreads();
    }

    // epilogue: c0:(g,2t) c1:(g,2t+1) c2:(g+8,2t) c3:(g+8,2t+1)
#pragma unroll
    for (int mi = 0; mi < 2; mi++) {
        int rbase = row0 + wm * 32 + mi * 16;
        int rA = rbase + g, rB = rbase + g + 8;
        size_t natA = 0, natB = 0;
        if (MODE == 2) { natA = nat_index(rA) * (size_t)CDIM; natB = nat_index(rB) * (size_t)CDIM; }
#pragma unroll
        for (int ni = 0; ni < 4; ni++) {
#pragma unroll
            for (int e = 0; e < 4; e++) {
                int row = (e & 2) ? rB : rA;
                int col = col0 + wn * 32 + ni * 8 + 2 * t + (e & 1);
                if (col >= N) continue;
                float v = acc[mi][ni][e];
                if (MODE == 0) {
                    C[(size_t)row * N + col] = v;
                } else if (MODE == 1) {
                    C[(size_t)row * N + col] = gelu_tanh(v + bias[col]);
                } else if (MODE == 2) {
                    size_t o = ((e & 2) ? natB : natA) + col;
                    C[o] = res[o] + v + bias[col];
                } else {
                    size_t o = (size_t)row * N + col;
                    C[o] = C[o] + v + bias[col];
                }
            }
        }
    }
}

// ---------------- attention ----------------
__device__ __forceinline__ int region3(int d, int h, int w) {
    int rd = (d < 6)   ? 0 : (d < 7   ? 1 : 2);
    int rh = (h < 120) ? 0 : (h < 124 ? 1 : 2);
    int rw = (w < 120) ? 0 : (w < 124 ? 1 : 2);
    return rd * 9 + rh * 3 + rw;
}

#define ATTN_SMEM ((128*33 + 128*33 + 128*129 + 675 + 128) * 4)

__global__ void attn_kernel(const float* __restrict__ qkv,
                            const float* __restrict__ rel_bias,
                            float* __restrict__ attn_out) {
    extern __shared__ float sm[];
    float* ks     = sm;
    float* vs     = ks + 128 * 33;
    float* ps     = vs + 128 * 33;
    float* bias_s = ps + 128 * 129;
    int*   reg_s  = (int*)(bias_s + 675);

    int blk  = blockIdx.x;
    int head = blk % HEADS;
    int bw   = blk / HEADS;
    int w    = bw % NWIN;
    int b    = bw / NWIN;
    int i    = threadIdx.x;

    const float* base = qkv + (size_t)(b * NWIN + w) * NTOK * QKVN;

    for (int idx = i; idx < 128 * 32; idx += 128) {
        int r = idx >> 5, c = idx & 31;
        ks[r * 33 + c] = base[(size_t)r * QKVN + 96  + head * 32 + c];
        vs[r * 33 + c] = base[(size_t)r * QKVN + 192 + head * 32 + c];
    }
    for (int t = i; t < 675; t += 128) bias_s[t] = rel_bias[t * 3 + head];
    {
        int wz = w >> 8, wy = (w >> 4) & 15, wx = w & 15;
        int td = i >> 6, th = (i >> 3) & 7, tw = i & 7;
        reg_s[i] = region3(wz * 2 + td, wy * 8 + th, wx * 8 + tw);
    }
    float qr[32];
#pragma unroll
    for (int dd = 0; dd < 32; dd++) qr[dd] = base[(size_t)i * QKVN + head * 32 + dd];
    __syncthreads();

    int myreg = reg_s[i];
    int di = i >> 6, hi = (i >> 3) & 7, wi = i & 7;

    float* prow = ps + i * 129;
    float mx = -1e30f;
    for (int j = 0; j < 128; j++) {
        const float* kj = ks + j * 33;
        float dot = 0.0f;
#pragma unroll
        for (int dd = 0; dd < 32; dd++) dot += qr[dd] * kj[dd];
        int dj = j >> 6, hj = (j >> 3) & 7, wj = j & 7;
        int bidx = (di - dj + 1) * 225 + (hi - hj + 7) * 15 + (wi - wj + 7);
        float sv = dot * ATT_SCALE + bias_s[bidx];
        sv += (reg_s[j] == myreg) ? 0.0f : -1e9f;
        prow[j] = sv;
        mx = fmaxf(mx, sv);
    }
    float den = 0.0f;
    for (int j = 0; j < 128; j++) {
        float p = __expf(prow[j] - mx);
        prow[j] = p;
        den += p;
    }
    float inv = 1.0f / den;
    float o[32] = {};
    for (int j = 0; j < 128; j++) {
        float p = prow[j];
        const float* vj = vs + j * 33;
#pragma unroll
        for (int dd = 0; dd < 32; dd++) o[dd] += p * vj[dd];
    }
    float* op = attn_out + (size_t)((b * NWIN + w) * NTOK + i) * INNER + head * 32;
#pragma unroll
    for (int dd = 0; dd < 32; dd++) op[dd] = o[dd] * inv;
}

// ---------------- launch ----------------
extern "C" void kernel_launch(void* const* d_in, const int* in_sizes, int n_in,
                              void* d_out, int out_size) {
    const float* x      = (const float*)d_in[0];
    const float* gamma1 = (const float*)d_in[1];
    const float* beta1  = (const float*)d_in[2];
    const float* w_qkv  = (const float*)d_in[3];
    const float* w_out  = (const float*)d_in[4];
    const float* b_out  = (const float*)d_in[5];
    const float* relb   = (const float*)d_in[6];
    const float* gamma2 = (const float*)d_in[7];
    const float* beta2  = (const float*)d_in[8];
    const float* w1     = (const float*)d_in[9];
    const float* b1     = (const float*)d_in[10];
    const float* w2     = (const float*)d_in[11];
    const float* b2     = (const float*)d_in[12];
    float* out = (float*)d_out;

    float *hw, *qkv, *attn, *h2, *mlp;
    cudaGetSymbolAddress((void**)&hw,   g_hw);
    cudaGetSymbolAddress((void**)&qkv,  g_qkv);
    cudaGetSymbolAddress((void**)&attn, g_attn);
    cudaGetSymbolAddress((void**)&h2,   g_h2);
    cudaGetSymbolAddress((void**)&mlp,  g_mlp);

    cudaFuncSetAttribute(attn_kernel, cudaFuncAttributeMaxDynamicSharedMemorySize,
                         ATTN_SMEM);

    ln_kernel<true><<<MROWS / 8, 256>>>(x, gamma1, beta1, hw);
    gemm_tc<0><<<dim3((QKVN + 63) / 64, MROWS / 128), 256>>>(
        hw, w_qkv, qkv, QKVN, CDIM, nullptr, nullptr);
    attn_kernel<<<BATCH * NWIN * HEADS, 128, ATTN_SMEM>>>(qkv, relb, attn);
    gemm_tc<2><<<dim3(2, MROWS / 128), 256>>>(
        attn, w_out, out, CDIM, INNER, b_out, x);
    ln_kernel<false><<<MROWS / 8, 256>>>(out, gamma2, beta2, h2);
    gemm_tc<1><<<dim3(MLPD / 64, MROWS / 128), 256>>>(
        h2, w1, mlp, MLPD, CDIM, b1, nullptr);
    gemm_tc<3><<<dim3(2, MROWS / 128), 256>>>(
        mlp, w2, out, CDIM, MLPD, b2, nullptr);
}

// round 3
// speedup vs baseline: 1.9190x; 1.5603x over previous
#include <cuda_runtime.h>
#include <cuda_bf16.h>
#include <math.h>
#include <stdint.h>

// ---------------- static config ----------------
#define BATCH  2
#define CDIM   96
#define HEADS  3
#define INNER  96
#define NWIN   1024
#define NTOK   128
#define MROWS  (BATCH*NWIN*NTOK)   // 262144
#define MLPD   384
#define QKVN   288
#define ATT_SCALE 0.17677669529663687f

typedef __nv_bfloat16 bf16;

// ---------------- scratch (bf16 intermediates) ----------------
__device__ bf16 g_hw  [(size_t)MROWS * CDIM];
__device__ bf16 g_qkv [(size_t)MROWS * QKVN];
__device__ bf16 g_attn[(size_t)MROWS * INNER];
__device__ bf16 g_h2  [(size_t)MROWS * CDIM];
__device__ bf16 g_mlp [(size_t)MROWS * MLPD];

__device__ __forceinline__ size_t nat_index(int r) {
    int bb  = r >> 17;
    int rem = r & 131071;
    int wdx = rem >> 7, n = rem & 127;
    int wz = wdx >> 8, wy = (wdx >> 4) & 15, wx = wdx & 15;
    int td = n >> 6,  th = (n >> 3) & 7,   tw = n & 7;
    int sd = (wz * 2 + td + 1) & 7;
    int sh = (wy * 8 + th + 4) & 127;
    int sw = (wx * 8 + tw + 4) & 127;
    return ((((size_t)bb * 8 + sd) << 7) | sh) << 7 | sw;
}

__device__ __forceinline__ float gelu_tanh(float v) {
    float c = v + 0.044715f * v * v * v;
    return 0.5f * v * (1.0f + tanhf(0.7978845608028654f * c));
}

__device__ __forceinline__ uint32_t f2tf32(float x) {
    uint32_t r;
    asm("cvt.rna.tf32.f32 %0, %1;" : "=r"(r) : "f"(x));
    return r;
}

__device__ __forceinline__ float2 bfpair(uint32_t u) {
    __nv_bfloat162 h = *reinterpret_cast<__nv_bfloat162*>(&u);
    return __bfloat1622float2(h);
}

// ---------------- LayerNorm (warp per token), bf16 output ----------------
template<bool GATHER>
__global__ void ln_kernel(const float* __restrict__ x,
                          const float* __restrict__ gamma,
                          const float* __restrict__ beta,
                          bf16* __restrict__ out) {
    int warp = (blockIdx.x * blockDim.x + threadIdx.x) >> 5;
    int lane = threadIdx.x & 31;
    if (warp >= MROWS) return;
    size_t src = GATHER ? nat_index(warp) : (size_t)warp;
    const float* xp = x + src * CDIM;
    float v0 = xp[lane], v1 = xp[lane + 32], v2 = xp[lane + 64];
    float s = v0 + v1 + v2;
#pragma unroll
    for (int o = 16; o; o >>= 1) s += __shfl_xor_sync(0xffffffffu, s, o);
    float mu = s * (1.0f / 96.0f);
    float d0 = v0 - mu, d1 = v1 - mu, d2 = v2 - mu;
    float q = d0 * d0 + d1 * d1 + d2 * d2;
#pragma unroll
    for (int o = 16; o; o >>= 1) q += __shfl_xor_sync(0xffffffffu, q, o);
    float rs = rsqrtf(q * (1.0f / 96.0f) + 1e-5f);
    bf16* op = out + (size_t)warp * CDIM;
    op[lane]      = __float2bfloat16(d0 * rs * gamma[lane]      + beta[lane]);
    op[lane + 32] = __float2bfloat16(d1 * rs * gamma[lane + 32] + beta[lane + 32]);
    op[lane + 64] = __float2bfloat16(d2 * rs * gamma[lane + 64] + beta[lane + 64]);
}

// ================= FULL-K GEMM (K=96): A[128x96] resident in smem, loop all N =====
// MODE 0: store bf16 (qkv)   MODE 1: +bias+gelu bf16 (fc1)
// MODE 2: +bias + res[nat] scatter, fp32 out (out-proj)
#define FK_SMEM ((128*100 + 96*72) * 4)
template<int MODE>
__global__ void __launch_bounds__(256)
gemm_fullk(const bf16* __restrict__ A, const float* __restrict__ B,
           void* __restrict__ Cv, int N,
           const float* __restrict__ bias, const float* __restrict__ res) {
    extern __shared__ uint32_t dsm[];
    uint32_t* As = dsm;                 // [128][100]  bank (4r+c)%32
    uint32_t* Bs = dsm + 128 * 100;     // [96][72]    bank (8r+c)%32
    int tid = threadIdx.x;
    int lane = tid & 31, wid = tid >> 5;
    int wm = wid & 3, wn = wid >> 2;
    int g = lane >> 2, t = lane & 3;
    int row0 = blockIdx.x * 128;

    // load A 128x96 bf16 -> fp32 bits (bf16 exact in tf32)
    {
        const uint32_t* a32 = (const uint32_t*)(A + (size_t)row0 * CDIM);
#pragma unroll
        for (int i = 0; i < 24; i++) {
            int lin = tid + i * 256;        // 6144 uint32
            int r = lin / 48, c = (lin % 48) * 2;
            float2 f = bfpair(a32[lin]);
            As[r * 100 + c]     = __float_as_uint(f.x);
            As[r * 100 + c + 1] = __float_as_uint(f.y);
        }
    }
    // precompute scatter indices once
    int rA_ = row0 + wm * 32 + g, rB_ = rA_ + 8;   // mi=0 rows
    size_t nat0A = 0, nat0B = 0, nat1A = 0, nat1B = 0;
    if (MODE == 2) {
        nat0A = nat_index(rA_) * (size_t)CDIM;
        nat0B = nat_index(rB_) * (size_t)CDIM;
        nat1A = nat_index(rA_ + 16) * (size_t)CDIM;
        nat1B = nat_index(rB_ + 16) * (size_t)CDIM;
    }

    int NT = (N + 63) / 64;
    for (int nt = 0; nt < NT; nt++) {
        int col0 = nt * 64;
        __syncthreads();
#pragma unroll
        for (int i = 0; i < 24; i++) {
            int lin = tid + i * 256;        // 96x64
            int r = lin >> 6, c = lin & 63;
            int gc = col0 + c;
            Bs[r * 72 + c] = (gc < N) ? f2tf32(B[(size_t)r * N + gc]) : 0u;
        }
        __syncthreads();

        float acc[2][4][4];
#pragma unroll
        for (int a = 0; a < 2; a++)
#pragma unroll
            for (int b = 0; b < 4; b++)
#pragma unroll
                for (int c = 0; c < 4; c++) acc[a][b][c] = 0.0f;

#pragma unroll
        for (int kk = 0; kk < 12; kk++) {
            uint32_t af[2][4], bf[4][2];
#pragma unroll
            for (int mi = 0; mi < 2; mi++) {
                int r = wm * 32 + mi * 16;
                af[mi][0] = As[(r + g) * 100 + kk * 8 + t];
                af[mi][1] = As[(r + g + 8) * 100 + kk * 8 + t];
                af[mi][2] = As[(r + g) * 100 + kk * 8 + t + 4];
                af[mi][3] = As[(r + g + 8) * 100 + kk * 8 + t + 4];
            }
#pragma unroll
            for (int ni = 0; ni < 4; ni++) {
                int cc = wn * 32 + ni * 8 + g;
                bf[ni][0] = Bs[(kk * 8 + t) * 72 + cc];
                bf[ni][1] = Bs[(kk * 8 + t + 4) * 72 + cc];
            }
#pragma unroll
            for (int mi = 0; mi < 2; mi++)
#pragma unroll
                for (int ni = 0; ni < 4; ni++) {
                    asm volatile(
                        "mma.sync.aligned.m16n8k8.row.col.f32.tf32.tf32.f32 "
                        "{%0,%1,%2,%3}, {%4,%5,%6,%7}, {%8,%9}, {%0,%1,%2,%3};\n"
                        : "+f"(acc[mi][ni][0]), "+f"(acc[mi][ni][1]),
                          "+f"(acc[mi][ni][2]), "+f"(acc[mi][ni][3])
                        : "r"(af[mi][0]), "r"(af[mi][1]), "r"(af[mi][2]), "r"(af[mi][3]),
                          "r"(bf[ni][0]), "r"(bf[ni][1]));
                }
        }
        // epilogue
#pragma unroll
        for (int mi = 0; mi < 2; mi++) {
            int rbase = row0 + wm * 32 + mi * 16;
            int rA = rbase + g, rB = rbase + g + 8;
            size_t natA = mi ? nat1A : nat0A;
            size_t natB = mi ? nat1B : nat0B;
#pragma unroll
            for (int ni = 0; ni < 4; ni++) {
#pragma unroll
                for (int e = 0; e < 4; e++) {
                    int row = (e & 2) ? rB : rA;
                    int col = col0 + wn * 32 + ni * 8 + 2 * t + (e & 1);
                    if (col >= N) continue;
                    float v = acc[mi][ni][e];
                    if (MODE == 0) {
                        ((bf16*)Cv)[(size_t)row * N + col] = __float2bfloat16(v);
                    } else if (MODE == 1) {
                        ((bf16*)Cv)[(size_t)row * N + col] =
                            __float2bfloat16(gelu_tanh(v + bias[col]));
                    } else {
                        size_t o = ((e & 2) ? natB : natA) + col;
                        ((float*)Cv)[o] = res[o] + v + bias[col];
                    }
                }
            }
        }
    }
}

// ================= K-loop GEMM for fc2: K=384, full N=96, C += v + bias ==========
__global__ void __launch_bounds__(256)
gemm_fc2(const bf16* __restrict__ A, const float* __restrict__ B,
         float* __restrict__ C, const float* __restrict__ bias) {
    __shared__ uint32_t As[128 * 36];   // bank (4r+c)
    __shared__ uint32_t Bs[32 * 104];   // bank (8r+c)
    int tid = threadIdx.x;
    int lane = tid & 31, wid = tid >> 5;
    int wm = wid & 3, wn = wid >> 2;
    int g = lane >> 2, t = lane & 3;
    int row0 = blockIdx.x * 128;

    float acc[2][6][4];
#pragma unroll
    for (int a = 0; a < 2; a++)
#pragma unroll
        for (int b = 0; b < 6; b++)
#pragma unroll
            for (int c = 0; c < 4; c++) acc[a][b][c] = 0.0f;

    for (int k0 = 0; k0 < MLPD; k0 += 32) {
        const uint32_t* a32 = (const uint32_t*)(A + (size_t)row0 * MLPD + k0);
#pragma unroll
        for (int i = 0; i < 8; i++) {
            int lin = tid + i * 256;          // 2048 uint32 = 128x32 bf16
            int r = lin >> 4, c2 = lin & 15;
            float2 f = bfpair(a32[(size_t)r * 192 + c2]);
            As[r * 36 + 2 * c2]     = __float_as_uint(f.x);
            As[r * 36 + 2 * c2 + 1] = __float_as_uint(f.y);
        }
#pragma unroll
        for (int i = 0; i < 12; i++) {
            int lin = tid + i * 256;          // 32x96
            int r = lin / 96, c = lin % 96;
            Bs[r * 104 + c] = f2tf32(B[(size_t)(k0 + r) * 96 + c]);
        }
        __syncthreads();
#pragma unroll
        for (int kk = 0; kk < 4; kk++) {
            uint32_t af[2][4], bf[6][2];
#pragma unroll
            for (int mi = 0; mi < 2; mi++) {
                int r = wm * 32 + mi * 16;
                af[mi][0] = As[(r + g) * 36 + kk * 8 + t];
                af[mi][1] = As[(r + g + 8) * 36 + kk * 8 + t];
                af[mi][2] = As[(r + g) * 36 + kk * 8 + t + 4];
                af[mi][3] = As[(r + g + 8) * 36 + kk * 8 + t + 4];
            }
#pragma unroll
            for (int ni = 0; ni < 6; ni++) {
                int cc = wn * 48 + ni * 8 + g;
                bf[ni][0] = Bs[(kk * 8 + t) * 104 + cc];
                bf[ni][1] = Bs[(kk * 8 + t + 4) * 104 + cc];
            }
#pragma unroll
            for (int mi = 0; mi < 2; mi++)
#pragma unroll
                for (int ni = 0; ni < 6; ni++) {
                    asm volatile(
                        "mma.sync.aligned.m16n8k8.row.col.f32.tf32.tf32.f32 "
                        "{%0,%1,%2,%3}, {%4,%5,%6,%7}, {%8,%9}, {%0,%1,%2,%3};\n"
                        : "+f"(acc[mi][ni][0]), "+f"(acc[mi][ni][1]),
                          "+f"(acc[mi][ni][2]), "+f"(acc[mi][ni][3])
                        : "r"(af[mi][0]), "r"(af[mi][1]), "r"(af[mi][2]), "r"(af[mi][3]),
                          "r"(bf[ni][0]), "r"(bf[ni][1]));
                }
        }
        __syncthreads();
    }
#pragma unroll
    for (int mi = 0; mi < 2; mi++) {
        int rbase = row0 + wm * 32 + mi * 16;
#pragma unroll
        for (int ni = 0; ni < 6; ni++) {
#pragma unroll
            for (int e = 0; e < 4; e++) {
                int row = rbase + g + ((e & 2) ? 8 : 0);
                int col = wn * 48 + ni * 8 + 2 * t + (e & 1);
                size_t o = (size_t)row * 96 + col;
                C[o] = C[o] + acc[mi][ni][e] + bias[col];
            }
        }
    }
}

// ---------------- attention: block per (batch, window, head) ----------------
__device__ __forceinline__ int region3(int d, int h, int w) {
    int rd = (d < 6)   ? 0 : (d < 7   ? 1 : 2);
    int rh = (h < 120) ? 0 : (h < 124 ? 1 : 2);
    int rw = (w < 120) ? 0 : (w < 124 ? 1 : 2);
    return rd * 9 + rh * 3 + rw;
}

#define ATTN_SMEM ((128*32 + 128*32 + 128*129 + 675 + 128) * 4)

__global__ void attn_kernel(const bf16* __restrict__ qkv,
                            const float* __restrict__ rel_bias,
                            bf16* __restrict__ attn_out) {
    extern __shared__ float sm[];
    float* ks     = sm;                   // [128][32]
    float* vs     = ks + 128 * 32;        // [128][32]
    float* ps     = vs + 128 * 32;        // [128][129]
    float* bias_s = ps + 128 * 129;       // 675
    int*   reg_s  = (int*)(bias_s + 675);

    int blk  = blockIdx.x;
    int head = blk % HEADS;
    int bw   = blk / HEADS;
    int w    = bw % NWIN;
    int b    = bw / NWIN;
    int i    = threadIdx.x;

    const bf16* base = qkv + (size_t)(b * NWIN + w) * NTOK * QKVN;
    const uint32_t* q32 = (const uint32_t*)base;   // row stride 144 u32

    for (int idx = i; idx < 128 * 16; idx += 128) {
        int r = idx >> 4, c2 = idx & 15;
        float2 fk = bfpair(q32[(size_t)r * 144 + 48 + head * 16 + c2]);
        float2 fv = bfpair(q32[(size_t)r * 144 + 96 + head * 16 + c2]);
        ks[r * 32 + 2 * c2] = fk.x; ks[r * 32 + 2 * c2 + 1] = fk.y;
        vs[r * 32 + 2 * c2] = fv.x; vs[r * 32 + 2 * c2 + 1] = fv.y;
    }
    for (int t = i; t < 675; t += 128) bias_s[t] = rel_bias[t * 3 + head];
    {
        int wz = w >> 8, wy = (w >> 4) & 15, wx = w & 15;
        int td = i >> 6, th = (i >> 3) & 7, tw = i & 7;
        reg_s[i] = region3(wz * 2 + td, wy * 8 + th, wx * 8 + tw);
    }
    float qr[32];
    {
        const uint32_t* qrow = q32 + (size_t)i * 144 + head * 16;
#pragma unroll
        for (int c2 = 0; c2 < 16; c2++) {
            float2 f = bfpair(qrow[c2]);
            qr[2 * c2] = f.x; qr[2 * c2 + 1] = f.y;
        }
    }
    __syncthreads();

    int myreg = reg_s[i];
    int di = i >> 6, hi = (i >> 3) & 7, wi = i & 7;

    float* prow = ps + i * 129;
    float mx = -1e30f;
    for (int j = 0; j < 128; j++) {
        const float4* kj = (const float4*)(ks + j * 32);
        float d0 = 0, d1 = 0, d2 = 0, d3 = 0;
#pragma unroll
        for (int c = 0; c < 8; c += 4) {
            float4 k0 = kj[c], k1 = kj[c + 1], k2 = kj[c + 2], k3 = kj[c + 3];
            d0 += qr[4*c+0]*k0.x + qr[4*c+1]*k0.y + qr[4*c+2]*k0.z + qr[4*c+3]*k0.w;
            d1 += qr[4*c+4]*k1.x + qr[4*c+5]*k1.y + qr[4*c+6]*k1.z + qr[4*c+7]*k1.w;
            d2 += qr[4*c+8]*k2.x + qr[4*c+9]*k2.y + qr[4*c+10]*k2.z + qr[4*c+11]*k2.w;
            d3 += qr[4*c+12]*k3.x + qr[4*c+13]*k3.y + qr[4*c+14]*k3.z + qr[4*c+15]*k3.w;
        }
        float dot = (d0 + d1) + (d2 + d3);
        int dj = j >> 6, hj = (j >> 3) & 7, wj = j & 7;
        int bidx = (di - dj + 1) * 225 + (hi - hj + 7) * 15 + (wi - wj + 7);
        float sv = dot * ATT_SCALE + bias_s[bidx];
        sv += (reg_s[j] == myreg) ? 0.0f : -1e9f;
        prow[j] = sv;
        mx = fmaxf(mx, sv);
    }
    float den = 0.0f;
    for (int j = 0; j < 128; j++) {
        float p = __expf(prow[j] - mx);
        prow[j] = p;
        den += p;
    }
    float inv = 1.0f / den;
    float o[32] = {};
    for (int j = 0; j < 128; j++) {
        float p = prow[j];
        const float4* vj = (const float4*)(vs + j * 32);
#pragma unroll
        for (int c = 0; c < 8; c++) {
            float4 v4 = vj[c];
            o[4*c]   += p * v4.x; o[4*c+1] += p * v4.y;
            o[4*c+2] += p * v4.z; o[4*c+3] += p * v4.w;
        }
    }
    bf16* op = attn_out + (size_t)((b * NWIN + w) * NTOK + i) * INNER + head * 32;
#pragma unroll
    for (int dd = 0; dd < 32; dd++) op[dd] = __float2bfloat16(o[dd] * inv);
}

// ---------------- launch ----------------
extern "C" void kernel_launch(void* const* d_in, const int* in_sizes, int n_in,
                              void* d_out, int out_size) {
    const float* x      = (const float*)d_in[0];
    const float* gamma1 = (const float*)d_in[1];
    const float* beta1  = (const float*)d_in[2];
    const float* w_qkv  = (const float*)d_in[3];
    const float* w_out  = (const float*)d_in[4];
    const float* b_out  = (const float*)d_in[5];
    const float* relb   = (const float*)d_in[6];
    const float* gamma2 = (const float*)d_in[7];
    const float* beta2  = (const float*)d_in[8];
    const float* w1     = (const float*)d_in[9];
    const float* b1     = (const float*)d_in[10];
    const float* w2     = (const float*)d_in[11];
    const float* b2     = (const float*)d_in[12];
    float* out = (float*)d_out;

    bf16 *hw, *qkv, *attn, *h2, *mlp;
    cudaGetSymbolAddress((void**)&hw,   g_hw);
    cudaGetSymbolAddress((void**)&qkv,  g_qkv);
    cudaGetSymbolAddress((void**)&attn, g_attn);
    cudaGetSymbolAddress((void**)&h2,   g_h2);
    cudaGetSymbolAddress((void**)&mlp,  g_mlp);

    cudaFuncSetAttribute(attn_kernel, cudaFuncAttributeMaxDynamicSharedMemorySize, ATTN_SMEM);
    cudaFuncSetAttribute(gemm_fullk<0>, cudaFuncAttributeMaxDynamicSharedMemorySize, FK_SMEM);
    cudaFuncSetAttribute(gemm_fullk<1>, cudaFuncAttributeMaxDynamicSharedMemorySize, FK_SMEM);
    cudaFuncSetAttribute(gemm_fullk<2>, cudaFuncAttributeMaxDynamicSharedMemorySize, FK_SMEM);

    ln_kernel<true><<<MROWS / 8, 256>>>(x, gamma1, beta1, hw);
    gemm_fullk<0><<<MROWS / 128, 256, FK_SMEM>>>(hw, w_qkv, qkv, QKVN, nullptr, nullptr);
    attn_kernel<<<BATCH * NWIN * HEADS, 128, ATTN_SMEM>>>(qkv, relb, attn);
    gemm_fullk<2><<<MROWS / 128, 256, FK_SMEM>>>(attn, w_out, out, CDIM, b_out, x);
    ln_kernel<false><<<MROWS / 8, 256>>>(out, gamma2, beta2, h2);
    gemm_fullk<1><<<MROWS / 128, 256, FK_SMEM>>>(h2, w1, mlp, MLPD, b1, nullptr);
    gemm_fc2<<<MROWS / 128, 256>>>(mlp, w2, out, b2);
}

// round 4
// speedup vs baseline: 5.3601x; 2.7932x over previous
#include <cuda_runtime.h>
#include <cuda_bf16.h>
#include <math.h>
#include <stdint.h>

// ---------------- static config ----------------
#define BATCH  2
#define CDIM   96
#define HEADS  3
#define INNER  96
#define NWIN   1024
#define NTOK   128
#define MROWS  (BATCH*NWIN*NTOK)   // 262144
#define MLPD   384
#define QKVN   288
#define ATT_SCALE 0.17677669529663687f

typedef __nv_bfloat16 bf16;

// ---------------- scratch ----------------
__device__ bf16 g_hw  [(size_t)MROWS * CDIM];
__device__ bf16 g_qkv [(size_t)MROWS * QKVN];
__device__ bf16 g_attn[(size_t)MROWS * INNER];
__device__ bf16 g_h2  [(size_t)MROWS * CDIM];
__device__ bf16 g_mlp [(size_t)MROWS * MLPD];
// weights, bf16, transposed [N][K/2] u32-packed (pair along K)
__device__ uint32_t g_wqkvT[QKVN * 48];
__device__ uint32_t g_w1T  [MLPD * 48];
__device__ uint32_t g_w2T  [96 * 192];
__device__ uint32_t g_woutT[96 * 48];

__device__ __forceinline__ size_t nat_index(int r) {
    int bb  = r >> 17;
    int rem = r & 131071;
    int wdx = rem >> 7, n = rem & 127;
    int wz = wdx >> 8, wy = (wdx >> 4) & 15, wx = wdx & 15;
    int td = n >> 6,  th = (n >> 3) & 7,   tw = n & 7;
    int sd = (wz * 2 + td + 1) & 7;
    int sh = (wy * 8 + th + 4) & 127;
    int sw = (wx * 8 + tw + 4) & 127;
    return ((((size_t)bb * 8 + sd) << 7) | sh) << 7 | sw;
}

__device__ __forceinline__ float gelu_tanh(float v) {
    float c = v + 0.044715f * v * v * v;
    return 0.5f * v * (1.0f + tanhf(0.7978845608028654f * c));
}

__device__ __forceinline__ uint32_t packbf(float a, float b) {
    __nv_bfloat162 h = __floats2bfloat162_rn(a, b);
    return *reinterpret_cast<uint32_t*>(&h);
}

#define MMA_BF16(d, a0, a1, a2, a3, b0, b1)                                   \
    asm volatile(                                                             \
        "mma.sync.aligned.m16n8k16.row.col.f32.bf16.bf16.f32 "                \
        "{%0,%1,%2,%3}, {%4,%5,%6,%7}, {%8,%9}, {%0,%1,%2,%3};\n"             \
        : "+f"(d[0]), "+f"(d[1]), "+f"(d[2]), "+f"(d[3])                      \
        : "r"(a0), "r"(a1), "r"(a2), "r"(a3), "r"(b0), "r"(b1))

// ---------------- weight convert: W[K][N] fp32 -> out[N][K/2] u32(bf16x2) ----
__global__ void convT(const float* __restrict__ W, uint32_t* __restrict__ out,
                      int K, int N) {
    int idx = blockIdx.x * 256 + threadIdx.x;
    int k2 = K >> 1;
    if (idx >= N * k2) return;
    int n = idx / k2, c = idx - n * k2;
    out[idx] = packbf(W[(2 * c) * N + n], W[(2 * c + 1) * N + n]);
}

// ---------------- LayerNorm (warp per token), bf16 output ----------------
template<bool GATHER>
__global__ void ln_kernel(const float* __restrict__ x,
                          const float* __restrict__ gamma,
                          const float* __restrict__ beta,
                          bf16* __restrict__ out) {
    int warp = (blockIdx.x * blockDim.x + threadIdx.x) >> 5;
    int lane = threadIdx.x & 31;
    if (warp >= MROWS) return;
    size_t src = GATHER ? nat_index(warp) : (size_t)warp;
    const float* xp = x + src * CDIM;
    float v0 = xp[lane], v1 = xp[lane + 32], v2 = xp[lane + 64];
    float s = v0 + v1 + v2;
#pragma unroll
    for (int o = 16; o; o >>= 1) s += __shfl_xor_sync(0xffffffffu, s, o);
    float mu = s * (1.0f / 96.0f);
    float d0 = v0 - mu, d1 = v1 - mu, d2 = v2 - mu;
    float q = d0 * d0 + d1 * d1 + d2 * d2;
#pragma unroll
    for (int o = 16; o; o >>= 1) q += __shfl_xor_sync(0xffffffffu, q, o);
    float rs = rsqrtf(q * (1.0f / 96.0f) + 1e-5f);
    bf16* op = out + (size_t)warp * CDIM;
    op[lane]      = __float2bfloat16(d0 * rs * gamma[lane]      + beta[lane]);
    op[lane + 32] = __float2bfloat16(d1 * rs * gamma[lane + 32] + beta[lane + 32]);
    op[lane + 64] = __float2bfloat16(d2 * rs * gamma[lane + 64] + beta[lane + 64]);
}

// ================= FULL-K bf16 GEMM (K=96): A[128x96] resident, loop N tiles ====
// MODE 0: bf16 store (qkv)  MODE 1: +bias+gelu bf16 (fc1)
// MODE 2: +bias + res[nat] scatter fp32 (out-proj)
template<int MODE>
__global__ void __launch_bounds__(256)
gemm_fullk(const bf16* __restrict__ A, const uint32_t* __restrict__ BT,
           void* __restrict__ Cv, int N,
           const float* __restrict__ bias, const float* __restrict__ res) {
    __shared__ uint32_t As[128 * 52];
    __shared__ uint32_t Bs[64 * 52];
    int tid = threadIdx.x;
    int lane = tid & 31, wid = tid >> 5;
    int wm = wid & 3, wn = wid >> 2;
    int g = lane >> 2, t = lane & 3;
    int row0 = blockIdx.x * 128;

    // stage A (bf16 pairs, no conversion)
    const uint32_t* a32 = (const uint32_t*)(A + (size_t)row0 * CDIM);
#pragma unroll
    for (int i = 0; i < 24; i++) {
        int lin = tid + i * 256;
        int r = lin / 48, c = lin - r * 48;
        As[r * 52 + c] = a32[lin];
    }

    size_t nat0A = 0, nat0B = 0, nat1A = 0, nat1B = 0;
    if (MODE == 2) {
        int rA = row0 + wm * 32 + g;
        nat0A = nat_index(rA) * (size_t)CDIM;
        nat0B = nat_index(rA + 8) * (size_t)CDIM;
        nat1A = nat_index(rA + 16) * (size_t)CDIM;
        nat1B = nat_index(rA + 24) * (size_t)CDIM;
    }

    int NT = (N + 63) >> 6;
    for (int nt = 0; nt < NT; nt++) {
        int col0 = nt * 64;
        __syncthreads();
#pragma unroll
        for (int i = 0; i < 12; i++) {
            int lin = tid + i * 256;
            int n = lin / 48, c = lin - n * 48;
            Bs[n * 52 + c] = (col0 + n < N) ? BT[(size_t)(col0 + n) * 48 + c] : 0u;
        }
        __syncthreads();

        float acc[2][4][4];
#pragma unroll
        for (int a = 0; a < 2; a++)
#pragma unroll
            for (int b = 0; b < 4; b++)
#pragma unroll
                for (int c = 0; c < 4; c++) acc[a][b][c] = 0.0f;

#pragma unroll
        for (int kk = 0; kk < 6; kk++) {
            uint32_t af[2][4];
#pragma unroll
            for (int mi = 0; mi < 2; mi++) {
                int base = (wm * 32 + mi * 16 + g) * 52 + kk * 8 + t;
                af[mi][0] = As[base];
                af[mi][1] = As[base + 8 * 52];
                af[mi][2] = As[base + 4];
                af[mi][3] = As[base + 8 * 52 + 4];
            }
#pragma unroll
            for (int ni = 0; ni < 4; ni++) {
                int nb = (wn * 32 + ni * 8 + g) * 52 + kk * 8 + t;
                uint32_t b0 = Bs[nb], b1 = Bs[nb + 4];
#pragma unroll
                for (int mi = 0; mi < 2; mi++)
                    MMA_BF16(acc[mi][ni], af[mi][0], af[mi][1], af[mi][2], af[mi][3], b0, b1);
            }
        }
        // epilogue (col pairs 2t,2t+1 are adjacent -> packed stores)
#pragma unroll
        for (int mi = 0; mi < 2; mi++) {
            int rbase = row0 + wm * 32 + mi * 16;
            int rA = rbase + g, rB = rbase + g + 8;
            size_t natA = mi ? nat1A : nat0A;
            size_t natB = mi ? nat1B : nat0B;
#pragma unroll
            for (int ni = 0; ni < 4; ni++) {
                int cc = col0 + wn * 32 + ni * 8 + 2 * t;
                if (cc >= N) continue;
                float v0 = acc[mi][ni][0], v1 = acc[mi][ni][1];
                float v2 = acc[mi][ni][2], v3 = acc[mi][ni][3];
                if (MODE == 0) {
                    ((uint32_t*)Cv)[((size_t)rA * N + cc) >> 1] = packbf(v0, v1);
                    ((uint32_t*)Cv)[((size_t)rB * N + cc) >> 1] = packbf(v2, v3);
                } else if (MODE == 1) {
                    float b0 = bias[cc], b1 = bias[cc + 1];
                    ((uint32_t*)Cv)[((size_t)rA * N + cc) >> 1] =
                        packbf(gelu_tanh(v0 + b0), gelu_tanh(v1 + b1));
                    ((uint32_t*)Cv)[((size_t)rB * N + cc) >> 1] =
                        packbf(gelu_tanh(v2 + b0), gelu_tanh(v3 + b1));
                } else {
                    float b0 = bias[cc], b1 = bias[cc + 1];
                    float2 rx = *(const float2*)(res + natA + cc);
                    float2 ry = *(const float2*)(res + natB + cc);
                    *(float2*)((float*)Cv + natA + cc) = make_float2(rx.x + v0 + b0, rx.y + v1 + b1);
                    *(float2*)((float*)Cv + natB + cc) = make_float2(ry.x + v2 + b0, ry.y + v3 + b1);
                }
            }
        }
    }
}

// ================= fc2: K=384, N=96, C += v + bias (bf16 mma) ==========
__global__ void __launch_bounds__(256)
gemm_fc2(const bf16* __restrict__ A, const uint32_t* __restrict__ BT,
         float* __restrict__ C, const float* __restrict__ bias) {
    __shared__ uint32_t As[128 * 36];
    __shared__ uint32_t Bs[96 * 36];
    int tid = threadIdx.x;
    int lane = tid & 31, wid = tid >> 5;
    int wm = wid & 3, wn = wid >> 2;
    int g = lane >> 2, t = lane & 3;
    int row0 = blockIdx.x * 128;

    float acc[2][6][4];
#pragma unroll
    for (int a = 0; a < 2; a++)
#pragma unroll
        for (int b = 0; b < 6; b++)
#pragma unroll
            for (int c = 0; c < 4; c++) acc[a][b][c] = 0.0f;

    for (int k0 = 0; k0 < 192; k0 += 32) {     // k2 chunks of 32 u32 = 64 bf16
        const uint32_t* a32 = (const uint32_t*)(A + (size_t)row0 * MLPD) + k0;
        __syncthreads();
#pragma unroll
        for (int i = 0; i < 16; i++) {
            int lin = tid + i * 256;
            int r = lin >> 5, c = lin & 31;
            As[r * 36 + c] = a32[(size_t)r * 192 + c];
        }
#pragma unroll
        for (int i = 0; i < 12; i++) {
            int lin = tid + i * 256;
            int n = lin >> 5, c = lin & 31;
            Bs[n * 36 + c] = BT[(size_t)n * 192 + k0 + c];
        }
        __syncthreads();
#pragma unroll
        for (int kk = 0; kk < 4; kk++) {
            uint32_t af[2][4];
#pragma unroll
            for (int mi = 0; mi < 2; mi++) {
                int base = (wm * 32 + mi * 16 + g) * 36 + kk * 8 + t;
                af[mi][0] = As[base];
                af[mi][1] = As[base + 8 * 36];
                af[mi][2] = As[base + 4];
                af[mi][3] = As[base + 8 * 36 + 4];
            }
#pragma unroll
            for (int ni = 0; ni < 6; ni++) {
                int nb = (wn * 48 + ni * 8 + g) * 36 + kk * 8 + t;
                uint32_t b0 = Bs[nb], b1 = Bs[nb + 4];
#pragma unroll
                for (int mi = 0; mi < 2; mi++)
                    MMA_BF16(acc[mi][ni], af[mi][0], af[mi][1], af[mi][2], af[mi][3], b0, b1);
            }
        }
    }
#pragma unroll
    for (int mi = 0; mi < 2; mi++) {
        int rbase = row0 + wm * 32 + mi * 16;
#pragma unroll
        for (int ni = 0; ni < 6; ni++) {
            int cc = wn * 48 + ni * 8 + 2 * t;
            float b0 = bias[cc], b1 = bias[cc + 1];
            size_t oA = (size_t)(rbase + g) * 96 + cc;
            size_t oB = (size_t)(rbase + g + 8) * 96 + cc;
            float2 ca = *(float2*)(C + oA);
            float2 cb = *(float2*)(C + oB);
            *(float2*)(C + oA) = make_float2(ca.x + acc[mi][ni][0] + b0,
                                             ca.y + acc[mi][ni][1] + b1);
            *(float2*)(C + oB) = make_float2(cb.x + acc[mi][ni][2] + b0,
                                             cb.y + acc[mi][ni][3] + b1);
        }
    }
}

// ---------------- attention: tensor-core, scores in registers ----------------
__device__ __forceinline__ int region3(int d, int h, int w) {
    int rd = (d < 6)   ? 0 : (d < 7   ? 1 : 2);
    int rh = (h < 120) ? 0 : (h < 124 ? 1 : 2);
    int rw = (w < 120) ? 0 : (w < 124 ? 1 : 2);
    return rd * 9 + rh * 3 + rw;
}

__global__ void attn_kernel(const bf16* __restrict__ qkv,
                            const float* __restrict__ rel_bias,
                            bf16* __restrict__ attn_out) {
    __shared__ uint32_t Qs[128 * 20];
    __shared__ uint32_t Ks[128 * 20];
    __shared__ bf16     VsT[32 * 136];
    __shared__ float    bias_s[675];
    __shared__ int      colPk[128];

    int blk  = blockIdx.x;
    int head = blk % HEADS;
    int bw   = blk / HEADS;          // b*NWIN + w
    int w    = bw & (NWIN - 1);
    int i    = threadIdx.x;
    int lane = i & 31, wm = i >> 5;
    int g = lane >> 2, t = lane & 3;

    const uint32_t* q32 = (const uint32_t*)(qkv + (size_t)bw * NTOK * QKVN); // row stride 144

#pragma unroll
    for (int it = 0; it < 16; it++) {
        int idx = i + it * 128;
        int r = idx >> 4, c = idx & 15;
        Qs[r * 20 + c] = q32[(size_t)r * 144 + head * 16 + c];
        Ks[r * 20 + c] = q32[(size_t)r * 144 + 48 + head * 16 + c];
        uint32_t v = q32[(size_t)r * 144 + 96 + head * 16 + c];
        __nv_bfloat162 h = *reinterpret_cast<__nv_bfloat162*>(&v);
        VsT[(2 * c) * 136 + r]     = h.x;
        VsT[(2 * c + 1) * 136 + r] = h.y;
    }
    for (int tt = i; tt < 675; tt += 128) bias_s[tt] = rel_bias[tt * 3 + head];
    {
        int dj = i >> 6, hj = (i >> 3) & 7, wj = i & 7;
        int off = dj * 225 + hj * 15 + wj;
        int wz = w >> 8, wy = (w >> 4) & 15, wx = w & 15;
        int rg = region3(wz * 2 + dj, wy * 8 + hj, wx * 8 + wj);
        colPk[i] = off | (rg << 16);
    }
    __syncthreads();

    // ---- S = Q K^T  (128x128x32) ----
    float accS[2][16][4];
#pragma unroll
    for (int a = 0; a < 2; a++)
#pragma unroll
        for (int b = 0; b < 16; b++)
#pragma unroll
            for (int c = 0; c < 4; c++) accS[a][b][c] = 0.0f;

#pragma unroll
    for (int kk = 0; kk < 2; kk++) {
        uint32_t af[2][4];
#pragma unroll
        for (int mi = 0; mi < 2; mi++) {
            int base = (wm * 32 + mi * 16 + g) * 20 + kk * 8 + t;
            af[mi][0] = Qs[base];
            af[mi][1] = Qs[base + 8 * 20];
            af[mi][2] = Qs[base + 4];
            af[mi][3] = Qs[base + 8 * 20 + 4];
        }
#pragma unroll
        for (int nj = 0; nj < 16; nj++) {
            int nb = (nj * 8 + g) * 20 + kk * 8 + t;
            uint32_t b0 = Ks[nb], b1 = Ks[nb + 4];
#pragma unroll
            for (int mi = 0; mi < 2; mi++)
                MMA_BF16(accS[mi][nj], af[mi][0], af[mi][1], af[mi][2], af[mi][3], b0, b1);
        }
    }

    // ---- bias + mask + softmax (rows g / g+8 per mi) ----
    float invA[2], invB[2];
    int pc0 = colPk[2 * t];      // col offsets repeat with period 8; cols = nj*8+2t
#pragma unroll
    for (int mi = 0; mi < 2; mi++) {
        int R0 = wm * 32 + mi * 16 + g;
        int pkA = colPk[R0], pkB = colPk[R0 + 8];
        int rowOffA = (pkA & 0xffff) + 337, regA = pkA >> 16;
        int rowOffB = (pkB & 0xffff) + 337, regB = pkB >> 16;
        float mA = -1e30f, mB = -1e30f;
#pragma unroll
        for (int nj = 0; nj < 16; nj++) {
            int c0 = nj * 8 + 2 * t;
            int pk0 = colPk[c0], pk1 = colPk[c0 + 1];
            int o0 = pk0 & 0xffff, r0 = pk0 >> 16;
            int o1 = pk1 & 0xffff, r1 = pk1 >> 16;
            float v0 = accS[mi][nj][0] * ATT_SCALE + bias_s[rowOffA - o0] + (r0 == regA ? 0.f : -1e9f);
            float v1 = accS[mi][nj][1] * ATT_SCALE + bias_s[rowOffA - o1] + (r1 == regA ? 0.f : -1e9f);
            float v2 = accS[mi][nj][2] * ATT_SCALE + bias_s[rowOffB - o0] + (r0 == regB ? 0.f : -1e9f);
            float v3 = accS[mi][nj][3] * ATT_SCALE + bias_s[rowOffB - o1] + (r1 == regB ? 0.f : -1e9f);
            accS[mi][nj][0] = v0; accS[mi][nj][1] = v1;
            accS[mi][nj][2] = v2; accS[mi][nj][3] = v3;
            mA = fmaxf(mA, fmaxf(v0, v1));
            mB = fmaxf(mB, fmaxf(v2, v3));
        }
        mA = fmaxf(mA, __shfl_xor_sync(0xffffffffu, mA, 1));
        mA = fmaxf(mA, __shfl_xor_sync(0xffffffffu, mA, 2));
        mB = fmaxf(mB, __shfl_xor_sync(0xffffffffu, mB, 1));
        mB = fmaxf(mB, __shfl_xor_sync(0xffffffffu, mB, 2));
        float dA = 0.f, dB = 0.f;
#pragma unroll
        for (int nj = 0; nj < 16; nj++) {
            float p0 = __expf(accS[mi][nj][0] - mA);
            float p1 = __expf(accS[mi][nj][1] - mA);
            float p2 = __expf(accS[mi][nj][2] - mB);
            float p3 = __expf(accS[mi][nj][3] - mB);
            accS[mi][nj][0] = p0; accS[mi][nj][1] = p1;
            accS[mi][nj][2] = p2; accS[mi][nj][3] = p3;
            dA += p0 + p1; dB += p2 + p3;
        }
        dA += __shfl_xor_sync(0xffffffffu, dA, 1);
        dA += __shfl_xor_sync(0xffffffffu, dA, 2);
        dB += __shfl_xor_sync(0xffffffffu, dB, 1);
        dB += __shfl_xor_sync(0xffffffffu, dB, 2);
        invA[mi] = 1.0f / dA;
        invB[mi] = 1.0f / dB;
    }
    (void)pc0;

    // ---- O = P V  (128x32x128); S C-frags repack directly into A-frags ----
    const uint32_t* vs32 = (const uint32_t*)VsT;   // row stride 68 u32
    float accO[2][4][4];
#pragma unroll
    for (int a = 0; a < 2; a++)
#pragma unroll
        for (int b = 0; b < 4; b++)
#pragma unroll
            for (int c = 0; c < 4; c++) accO[a][b][c] = 0.0f;

#pragma unroll
    for (int kkp = 0; kkp < 8; kkp++) {
        uint32_t af[2][4];
#pragma unroll
        for (int mi = 0; mi < 2; mi++) {
            af[mi][0] = packbf(accS[mi][2 * kkp][0],     accS[mi][2 * kkp][1]);
            af[mi][1] = packbf(accS[mi][2 * kkp][2],     accS[mi][2 * kkp][3]);
            af[mi][2] = packbf(accS[mi][2 * kkp + 1][0], accS[mi][2 * kkp + 1][1]);
            af[mi][3] = packbf(accS[mi][2 * kkp + 1][2], accS[mi][2 * kkp + 1][3]);
        }
#pragma unroll
        for (int ni = 0; ni < 4; ni++) {
            int vb = (ni * 8 + g) * 68 + kkp * 8 + t;
            uint32_t b0 = vs32[vb], b1 = vs32[vb + 4];
#pragma unroll
            for (int mi = 0; mi < 2; mi++)
                MMA_BF16(accO[mi][ni], af[mi][0], af[mi][1], af[mi][2], af[mi][3], b0, b1);
        }
    }

    // ---- normalize + store bf16 (u32-packed) ----
    uint32_t* o32 = (uint32_t*)attn_out;   // row stride 48 u32
#pragma unroll
    for (int mi = 0; mi < 2; mi++) {
        int R0 = wm * 32 + mi * 16 + g;
        size_t baseA = ((size_t)bw * 128 + R0) * 48 + head * 16;
        size_t baseB = baseA + 8 * 48;
#pragma unroll
        for (int ni = 0; ni < 4; ni++) {
            int c2 = ni * 4 + t;
            o32[baseA + c2] = packbf(accO[mi][ni][0] * invA[mi], accO[mi][ni][1] * invA[mi]);
            o32[baseB + c2] = packbf(accO[mi][ni][2] * invB[mi], accO[mi][ni][3] * invB[mi]);
        }
    }
}

// ---------------- launch ----------------
extern "C" void kernel_launch(void* const* d_in, const int* in_sizes, int n_in,
                              void* d_out, int out_size) {
    const float* x      = (const float*)d_in[0];
    const float* gamma1 = (const float*)d_in[1];
    const float* beta1  = (const float*)d_in[2];
    const float* w_qkv  = (const float*)d_in[3];
    const float* w_out  = (const float*)d_in[4];
    const float* b_out  = (const float*)d_in[5];
    const float* relb   = (const float*)d_in[6];
    const float* gamma2 = (const float*)d_in[7];
    const float* beta2  = (const float*)d_in[8];
    const float* w1     = (const float*)d_in[9];
    const float* b1     = (const float*)d_in[10];
    const float* w2     = (const float*)d_in[11];
    const float* b2     = (const float*)d_in[12];
    float* out = (float*)d_out;

    bf16 *hw, *qkv, *attn, *h2, *mlp;
    uint32_t *wqkvT, *w1T, *w2T, *woutT;
    cudaGetSymbolAddress((void**)&hw,    g_hw);
    cudaGetSymbolAddress((void**)&qkv,   g_qkv);
    cudaGetSymbolAddress((void**)&attn,  g_attn);
    cudaGetSymbolAddress((void**)&h2,    g_h2);
    cudaGetSymbolAddress((void**)&mlp,   g_mlp);
    cudaGetSymbolAddress((void**)&wqkvT, g_wqkvT);
    cudaGetSymbolAddress((void**)&w1T,   g_w1T);
    cudaGetSymbolAddress((void**)&w2T,   g_w2T);
    cudaGetSymbolAddress((void**)&woutT, g_woutT);

    convT<<<(QKVN * 48 + 255) / 256, 256>>>(w_qkv, wqkvT, 96, QKVN);
    convT<<<(MLPD * 48 + 255) / 256, 256>>>(w1, w1T, 96, MLPD);
    convT<<<(96 * 192 + 255) / 256, 256>>>(w2, w2T, 384, 96);
    convT<<<(96 * 48 + 255) / 256, 256>>>(w_out, woutT, 96, 96);

    ln_kernel<true><<<MROWS / 8, 256>>>(x, gamma1, beta1, hw);
    gemm_fullk<0><<<MROWS / 128, 256>>>(hw, wqkvT, qkv, QKVN, nullptr, nullptr);
    attn_kernel<<<BATCH * NWIN * HEADS, 128>>>(qkv, relb, attn);
    gemm_fullk<2><<<MROWS / 128, 256>>>(attn, woutT, out, CDIM, b_out, x);
    ln_kernel<false><<<MROWS / 8, 256>>>(out, gamma2, beta2, h2);
    gemm_fullk<1><<<MROWS / 128, 256>>>(h2, w1T, mlp, MLPD, b1, nullptr);
    gemm_fc2<<<MROWS / 128, 256>>>(mlp, w2T, out, b2);
}